// round 1
// baseline (speedup 1.0000x reference)
#include <cuda_runtime.h>
#include <math.h>

// Problem constants
#define BQ   4096     // both sides fused: [0,2048)=left, [2048,4096)=right
#define BH   2048
#define LVS  64
#define IND  300
#define M    150
#define M3   450
#define HIDD 50
#define NCC  5

#define RT   16       // rows per block (leaf)
#define TRT  16       // rows per block (tree)

// Ping-pong scratch for h/c state (uninitialized __device__ globals: no alloc at runtime)
__device__ float g_hA[BQ * LVS * M];
__device__ float g_cA[BQ * LVS * M];
__device__ float g_hB[BQ * (LVS / 2) * M];
__device__ float g_cB[BQ * (LVS / 2) * M];

__device__ __forceinline__ float sigf(float x) { return 1.0f / (1.0f + expf(-x)); }

// ---------------------------------------------------------------------------
// Leaf kernel: rows = BQ*LVS. x = emb[token]; iou = x@Wioux + bioux + biouh;
// c = sig(i)*tanh(u); h = sig(o)*tanh(c).
// Block: 128 threads, 16 rows, each thread owns cols {t, t+128, t+256, t+384}.
// ---------------------------------------------------------------------------
__global__ void __launch_bounds__(128) leaf_kernel(
    const int* __restrict__ ltok, const int* __restrict__ rtok,
    const float* __restrict__ emb,
    const float* __restrict__ Wx, const float* __restrict__ bx,
    const float* __restrict__ bhh,
    float* __restrict__ h_out, float* __restrict__ c_out)
{
    __shared__ float xs[RT][IND];        // 19200 B
    __shared__ float iou[RT][M3 + 2];    // 28928 B  (total 48128 < 49152)

    const int t = threadIdx.x;
    const int base = blockIdx.x * RT;

    // Gather x tile (coalesced per row)
    for (int idx = t; idx < RT * IND; idx += 128) {
        int rr = idx / IND, k = idx - rr * IND;
        int row = base + rr;
        int q = row >> 6, l = row & 63;
        int tok = (q < BH) ? ltok[q * LVS + l] : rtok[(q - BH) * LVS + l];
        xs[rr][k] = emb[tok * IND + k];
    }
    __syncthreads();

    float a0[RT], a1[RT], a2[RT], a3[RT];
#pragma unroll
    for (int rr = 0; rr < RT; rr++) { a0[rr] = 0.f; a1[rr] = 0.f; a2[rr] = 0.f; a3[rr] = 0.f; }

    const bool has3 = (t + 384) < M3;   // only t < 66
    for (int k = 0; k < IND; k++) {
        const float* wr = Wx + k * M3;
        float w0 = wr[t];
        float w1 = wr[t + 128];
        float w2 = wr[t + 256];
        float w3 = has3 ? wr[t + 384] : 0.f;
#pragma unroll
        for (int rr = 0; rr < RT; rr++) {
            float xv = xs[rr][k];
            a0[rr] += xv * w0;
            a1[rr] += xv * w1;
            a2[rr] += xv * w2;
            a3[rr] += xv * w3;
        }
    }

    float b0 = bx[t] + bhh[t];
    float b1 = bx[t + 128] + bhh[t + 128];
    float b2 = bx[t + 256] + bhh[t + 256];
    float b3 = has3 ? (bx[t + 384] + bhh[t + 384]) : 0.f;
#pragma unroll
    for (int rr = 0; rr < RT; rr++) {
        iou[rr][t]       = a0[rr] + b0;
        iou[rr][t + 128] = a1[rr] + b1;
        iou[rr][t + 256] = a2[rr] + b2;
        if (has3) iou[rr][t + 384] = a3[rr] + b3;
    }
    __syncthreads();

    for (int idx = t; idx < RT * M; idx += 128) {
        int rr = idx / M, j = idx - rr * M;
        float iv = sigf(iou[rr][j]);
        float ov = sigf(iou[rr][j + M]);
        float uv = tanhf(iou[rr][j + 2 * M]);
        float cv = iv * uv;
        float hv = ov * tanhf(cv);
        int row = base + rr;
        c_out[row * M + j] = cv;
        h_out[row * M + j] = hv;
    }
}

// ---------------------------------------------------------------------------
// Tree level kernel: output row r reads children rows 2r, 2r+1.
// iou = (h0+h1)@Wiouh + biouh ; f_k = sig(h_k@Wfh + bfh);
// c = sig(i)*tanh(u) + f0*c0 + f1*c1 ; h = sig(o)*tanh(c)
// Block: 256 threads, 16 rows. Thread t owns slots 3t..3t+2 of a fused
// 750-wide output: [0,450)=iou (from hs), [450,600)=f0 (h0), [600,750)=f1 (h1).
// Region boundaries are multiples of 3, so each thread's slots share a region.
// ---------------------------------------------------------------------------
__global__ void __launch_bounds__(256) tree_kernel(
    const float* __restrict__ h_in, const float* __restrict__ c_in,
    float* __restrict__ h_out, float* __restrict__ c_out,
    const float* __restrict__ Wiouh, const float* __restrict__ biouh,
    const float* __restrict__ Wfh, const float* __restrict__ bfh)
{
    __shared__ float sm[12100];         // 48400 B: tiles (7296 fl) then reused as res (12090 fl)
    const int t = threadIdx.x;
    const int base = blockIdx.x * TRT;

    float* HS = sm;
    float* H0 = sm + TRT * 152;
    float* H1 = sm + 2 * TRT * 152;

    for (int idx = t; idx < TRT * M; idx += 256) {
        int rr = idx / M, k = idx - rr * M;
        int orow = base + rr;
        float a = h_in[(2 * orow) * M + k];
        float b = h_in[(2 * orow + 1) * M + k];
        HS[rr * 152 + k] = a + b;
        H0[rr * 152 + k] = a;
        H1[rr * 152 + k] = b;
    }
    __syncthreads();

    const int slot0 = 3 * t;
    const int region = (slot0 < 450) ? 0 : ((slot0 < 600) ? 1 : 2);
    const bool active = slot0 < 750;

    const float* W;
    const float* tile;
    int colbase, ncols;
    if (region == 0)      { W = Wiouh; tile = HS; colbase = slot0;                       ncols = M3; }
    else if (region == 1) { W = Wfh;   tile = H0; colbase = slot0 - 450;                 ncols = M;  }
    else                  { W = Wfh;   tile = H1; colbase = active ? (slot0 - 600) : 0;  ncols = M;  }

    float a0[TRT], a1[TRT], a2[TRT];
#pragma unroll
    for (int rr = 0; rr < TRT; rr++) { a0[rr] = 0.f; a1[rr] = 0.f; a2[rr] = 0.f; }

    for (int k = 0; k < M; k++) {
        const float* wr = W + k * ncols + colbase;
        float w0 = wr[0], w1 = wr[1], w2 = wr[2];
        const float* tk = tile + k;
#pragma unroll
        for (int rr = 0; rr < TRT; rr++) {
            float v = tk[rr * 152];
            a0[rr] += v * w0;
            a1[rr] += v * w1;
            a2[rr] += v * w2;
        }
    }
    __syncthreads();   // tiles fully consumed; reuse sm as res[rr][756]

    if (active) {
        float bb0, bb1, bb2;
        if (region == 0) { bb0 = biouh[colbase]; bb1 = biouh[colbase + 1]; bb2 = biouh[colbase + 2]; }
        else             { bb0 = bfh[colbase];   bb1 = bfh[colbase + 1];   bb2 = bfh[colbase + 2];   }
#pragma unroll
        for (int rr = 0; rr < TRT; rr++) {
            sm[rr * 756 + slot0 + 0] = a0[rr] + bb0;
            sm[rr * 756 + slot0 + 1] = a1[rr] + bb1;
            sm[rr * 756 + slot0 + 2] = a2[rr] + bb2;
        }
    }
    __syncthreads();

    for (int idx = t; idx < TRT * M; idx += 256) {
        int rr = idx / M, j = idx - rr * M;
        const float* r = sm + rr * 756;
        float iv = sigf(r[j]);
        float ov = sigf(r[j + 150]);
        float uv = tanhf(r[j + 300]);
        float f0 = sigf(r[450 + j]);
        float f1 = sigf(r[600 + j]);
        int orow = base + rr;
        float c0 = c_in[(2 * orow) * M + j];
        float c1 = c_in[(2 * orow + 1) * M + j];
        float cv = iv * uv + f0 * c0 + f1 * c1;
        float hv = ov * tanhf(cv);
        c_out[orow * M + j] = cv;
        h_out[orow * M + j] = hv;
    }
}

// ---------------------------------------------------------------------------
// Classifier: vec = [lh*rh, |lh-rh|]; mid = sig(vec@Wh + bh);
// out = log_softmax(mid@Wp + bp). One block (64 thr) per pair.
// ---------------------------------------------------------------------------
__global__ void __launch_bounds__(64) cls_kernel(
    const float* __restrict__ hfin,
    const float* __restrict__ Wh, const float* __restrict__ bh,
    const float* __restrict__ Wp, const float* __restrict__ bp,
    float* __restrict__ out)
{
    __shared__ float vec[2 * M];
    __shared__ float mid[HIDD];
    __shared__ float logits[NCC];

    const int q = blockIdx.x;
    const int t = threadIdx.x;
    const float* lh = hfin + q * M;
    const float* rh = hfin + (BH + q) * M;

    for (int j = t; j < M; j += 64) {
        float a = lh[j], b = rh[j];
        vec[j]     = a * b;
        vec[M + j] = fabsf(a - b);
    }
    __syncthreads();

    if (t < HIDD) {
        float s = bh[t];
        for (int j = 0; j < 2 * M; j++) s += vec[j] * Wh[j * HIDD + t];
        mid[t] = sigf(s);
    }
    __syncthreads();

    if (t < NCC) {
        float s = bp[t];
        for (int h = 0; h < HIDD; h++) s += mid[h] * Wp[h * NCC + t];
        logits[t] = s;
    }
    __syncthreads();

    if (t == 0) {
        float mx = logits[0];
        for (int c = 1; c < NCC; c++) mx = fmaxf(mx, logits[c]);
        float sum = 0.f;
        for (int c = 0; c < NCC; c++) sum += expf(logits[c] - mx);
        float lse = mx + logf(sum);
        for (int c = 0; c < NCC; c++) out[q * NCC + c] = logits[c] - lse;
    }
}

// ---------------------------------------------------------------------------
extern "C" void kernel_launch(void* const* d_in, const int* in_sizes, int n_in,
                              void* d_out, int out_size)
{
    (void)in_sizes; (void)n_in; (void)out_size;
    const int*   ltok  = (const int*)d_in[0];
    const int*   rtok  = (const int*)d_in[1];
    const float* emb   = (const float*)d_in[2];
    const float* Wioux = (const float*)d_in[3];
    const float* bioux = (const float*)d_in[4];
    const float* Wiouh = (const float*)d_in[5];
    const float* biouh = (const float*)d_in[6];
    // d_in[7] = Wfx, d_in[8] = bfx : unused by the reference computation
    const float* Wfh   = (const float*)d_in[9];
    const float* bfh   = (const float*)d_in[10];
    const float* Wh    = (const float*)d_in[11];
    const float* bh    = (const float*)d_in[12];
    const float* Wp    = (const float*)d_in[13];
    const float* bp    = (const float*)d_in[14];
    float* out = (float*)d_out;

    void* p;
    float *hA, *cA, *hB, *cB;
    cudaGetSymbolAddress(&p, g_hA); hA = (float*)p;
    cudaGetSymbolAddress(&p, g_cA); cA = (float*)p;
    cudaGetSymbolAddress(&p, g_hB); hB = (float*)p;
    cudaGetSymbolAddress(&p, g_cB); cB = (float*)p;

    // Leaves: 4096*64 rows
    leaf_kernel<<<(BQ * LVS) / RT, 128>>>(ltok, rtok, emb, Wioux, bioux, biouh, hA, cA);

    // 6 tree levels, ping-pong A <-> B
    const float* hin = hA; const float* cin = cA;
    float* ho = hB; float* co = cB;
    for (int n_out = LVS / 2; n_out >= 1; n_out >>= 1) {
        tree_kernel<<<(BQ * n_out) / TRT, 256>>>(hin, cin, ho, co, Wiouh, biouh, Wfh, bfh);
        const float* th = hin; const float* tc = cin;
        hin = ho; cin = co;
        ho = (float*)th; co = (float*)tc;
    }
    // After 6 swaps, final state (4096 rows x 150) is in hin (= g_hA)

    cls_kernel<<<BH, 64>>>(hin, Wh, bh, Wp, bp, out);
}

// round 2
// speedup vs baseline: 1.8233x; 1.8233x over previous
#include <cuda_runtime.h>
#include <math.h>

// Problem constants
#define BQ   4096     // both sides fused: [0,2048)=left, [2048,4096)=right
#define BH   2048
#define LVS  64
#define IND  300
#define M    150
#define M3   450
#define HIDD 50
#define NCC  5
#define VMAX 50000

#define TRT  16       // rows per block (tree)
#define VRT  32       // rows per block (vocab GEMM)

// Scratch (uninitialized __device__ globals: no runtime allocation)
__device__ float g_table[VMAX * M3];            // 90 MB: iou(token) with biases folded
__device__ float g_hA[BQ * LVS * M];
__device__ float g_cA[BQ * LVS * M];
__device__ float g_hB[BQ * (LVS / 2) * M];
__device__ float g_cB[BQ * (LVS / 2) * M];

__device__ __forceinline__ float sigf(float x) { return 1.0f / (1.0f + expf(-x)); }

// ---- packed f32x2 helpers (sm_100+) --------------------------------------
__device__ __forceinline__ void ffma2(unsigned long long& acc,
                                      unsigned long long a,
                                      unsigned long long b) {
    asm("fma.rn.f32x2 %0, %1, %2, %0;" : "+l"(acc) : "l"(a), "l"(b));
}
__device__ __forceinline__ unsigned long long pack2(float x, float y) {
    unsigned long long r;
    asm("mov.b64 %0, {%1, %2};" : "=l"(r) : "f"(x), "f"(y));
    return r;
}
__device__ __forceinline__ float2 unpack2(unsigned long long v) {
    float2 f;
    asm("mov.b64 {%0, %1}, %2;" : "=f"(f.x), "=f"(f.y) : "l"(v));
    return f;
}

// ---------------------------------------------------------------------------
// Vocab GEMM: table[v] = emb[v] @ Wioux + (bioux + biouh), v in [0, V).
// 256 threads, 32 rows/block. Thread t owns cols {t, t+256}.
// xs transposed [k][rr] with stride 36 (16B-aligned, 4-way STS conflicts only).
// Accumulate row-pairs in f32x2.
// ---------------------------------------------------------------------------
__global__ void __launch_bounds__(256) vocab_kernel(
    const float* __restrict__ emb,
    const float* __restrict__ Wx, const float* __restrict__ bx,
    const float* __restrict__ bhh,
    float* __restrict__ table, int V)
{
    __shared__ __align__(16) float xs[IND * 36];   // 43200 B

    const int t = threadIdx.x;
    const int base = blockIdx.x * VRT;

    for (int idx = t; idx < VRT * IND; idx += 256) {
        int rr = idx / IND, k = idx - rr * IND;
        int row = base + rr;
        if (row >= V) row = V - 1;
        xs[k * 36 + rr] = emb[row * IND + k];
    }
    __syncthreads();

    unsigned long long a0[16], a1[16];
#pragma unroll
    for (int i = 0; i < 16; i++) { a0[i] = 0ull; a1[i] = 0ull; }

    const bool has1 = (t + 256) < M3;   // t < 194
    for (int k = 0; k < IND; k++) {
        const float* wr = Wx + k * M3;
        float w0 = wr[t];
        float w1 = has1 ? wr[t + 256] : 0.f;
        unsigned long long pw0 = pack2(w0, w0);
        unsigned long long pw1 = pack2(w1, w1);
        const ulonglong2* xp = reinterpret_cast<const ulonglong2*>(xs + k * 36);
#pragma unroll
        for (int p = 0; p < 8; p++) {
            ulonglong2 v = xp[p];                 // rows 4p..4p+3
            ffma2(a0[2 * p],     v.x, pw0);
            ffma2(a0[2 * p + 1], v.y, pw0);
            ffma2(a1[2 * p],     v.x, pw1);
            ffma2(a1[2 * p + 1], v.y, pw1);
        }
    }

    float b0 = bx[t] + bhh[t];
    float b1 = has1 ? (bx[t + 256] + bhh[t + 256]) : 0.f;
#pragma unroll
    for (int pr = 0; pr < 16; pr++) {
        int r0 = base + 2 * pr, r1 = r0 + 1;
        float2 v0 = unpack2(a0[pr]);
        if (r0 < V) table[r0 * M3 + t] = v0.x + b0;
        if (r1 < V) table[r1 * M3 + t] = v0.y + b0;
        if (has1) {
            float2 v1 = unpack2(a1[pr]);
            if (r0 < V) table[r0 * M3 + t + 256] = v1.x + b1;
            if (r1 < V) table[r1 * M3 + t + 256] = v1.y + b1;
        }
    }
}

// ---------------------------------------------------------------------------
// Leaf lookup: per element (row, j): read table[tok][{j, j+M, j+2M}], gates.
// Pure memory-bound; flat elementwise over BQ*LVS*M.
// ---------------------------------------------------------------------------
__global__ void __launch_bounds__(256) leaf_lookup_kernel(
    const int* __restrict__ ltok, const int* __restrict__ rtok,
    const float* __restrict__ table,
    float* __restrict__ h_out, float* __restrict__ c_out)
{
    int idx = blockIdx.x * 256 + threadIdx.x;     // < BQ*LVS*M = 39321600
    int row = idx / M;
    int j = idx - row * M;
    int q = row >> 6, l = row & 63;
    int tok = (q < BH) ? ltok[q * LVS + l] : rtok[(q - BH) * LVS + l];
    const float* tr = table + tok * M3;
    float iv = sigf(tr[j]);
    float ov = sigf(tr[j + M]);
    float uv = tanhf(tr[j + 2 * M]);
    float cv = iv * uv;
    float hv = ov * tanhf(cv);
    c_out[idx] = cv;
    h_out[idx] = hv;
}

// ---------------------------------------------------------------------------
// Tree level kernel (f32x2 + transposed tiles).
// Output row r reads children 2r, 2r+1.
// Fused 750-wide result: [0,450)=iou(hs), [450,600)=f0(h0), [600,750)=f1(h1).
// 256 threads, thread t owns slots 3t..3t+2 (region-uniform per thread).
// Tiles [k][rr] stride 20; LDS.128 pulls 4 row-values, broadcast across warp.
// ---------------------------------------------------------------------------
__global__ void __launch_bounds__(256) tree_kernel(
    const float* __restrict__ h_in, const float* __restrict__ c_in,
    float* __restrict__ h_out, float* __restrict__ c_out,
    const float* __restrict__ Wiouh, const float* __restrict__ biouh,
    const float* __restrict__ Wfh, const float* __restrict__ bfh)
{
    __shared__ __align__(16) float sm[12096];   // 48384 B; tiles use first 9000 floats
    const int t = threadIdx.x;
    const int base = blockIdx.x * TRT;

    float* HS = sm;            // [k*20 + rr]
    float* H0 = sm + 3000;
    float* H1 = sm + 6000;

    for (int idx = t; idx < TRT * M; idx += 256) {
        int rr = idx / M, k = idx - rr * M;
        int orow = base + rr;
        float a = h_in[(2 * orow) * M + k];
        float b = h_in[(2 * orow + 1) * M + k];
        HS[k * 20 + rr] = a + b;
        H0[k * 20 + rr] = a;
        H1[k * 20 + rr] = b;
    }
    __syncthreads();

    const int slot0 = 3 * t;
    const int region = (slot0 < 450) ? 0 : ((slot0 < 600) ? 1 : 2);
    const bool active = slot0 < 750;

    const float* W;
    const float* tile;
    int colbase, ncols;
    if (region == 0)      { W = Wiouh; tile = HS; colbase = slot0;                      ncols = M3; }
    else if (region == 1) { W = Wfh;   tile = H0; colbase = slot0 - 450;                ncols = M;  }
    else                  { W = Wfh;   tile = H1; colbase = active ? (slot0 - 600) : 0; ncols = M;  }

    unsigned long long a0[8], a1[8], a2[8];
#pragma unroll
    for (int i = 0; i < 8; i++) { a0[i] = 0ull; a1[i] = 0ull; a2[i] = 0ull; }

    for (int k = 0; k < M; k++) {
        const float* wr = W + k * ncols + colbase;
        float w0 = wr[0], w1 = wr[1], w2 = wr[2];
        unsigned long long pw0 = pack2(w0, w0);
        unsigned long long pw1 = pack2(w1, w1);
        unsigned long long pw2 = pack2(w2, w2);
        const ulonglong2* tp = reinterpret_cast<const ulonglong2*>(tile + k * 20);
#pragma unroll
        for (int p = 0; p < 4; p++) {
            ulonglong2 v = tp[p];                 // rows 4p..4p+3 (broadcast)
            ffma2(a0[2 * p],     v.x, pw0);
            ffma2(a0[2 * p + 1], v.y, pw0);
            ffma2(a1[2 * p],     v.x, pw1);
            ffma2(a1[2 * p + 1], v.y, pw1);
            ffma2(a2[2 * p],     v.x, pw2);
            ffma2(a2[2 * p + 1], v.y, pw2);
        }
    }
    __syncthreads();   // tiles fully consumed; reuse sm as res[rr][756]

    if (active) {
        float bb0, bb1, bb2;
        if (region == 0) { bb0 = biouh[colbase]; bb1 = biouh[colbase + 1]; bb2 = biouh[colbase + 2]; }
        else             { bb0 = bfh[colbase];   bb1 = bfh[colbase + 1];   bb2 = bfh[colbase + 2];   }
#pragma unroll
        for (int p = 0; p < 8; p++) {
            float2 v0 = unpack2(a0[p]);
            float2 v1 = unpack2(a1[p]);
            float2 v2 = unpack2(a2[p]);
            float* r0 = sm + (2 * p) * 756;
            float* r1 = sm + (2 * p + 1) * 756;
            r0[slot0]     = v0.x + bb0;  r1[slot0]     = v0.y + bb0;
            r0[slot0 + 1] = v1.x + bb1;  r1[slot0 + 1] = v1.y + bb1;
            r0[slot0 + 2] = v2.x + bb2;  r1[slot0 + 2] = v2.y + bb2;
        }
    }
    __syncthreads();

    for (int idx = t; idx < TRT * M; idx += 256) {
        int rr = idx / M, j = idx - rr * M;
        const float* r = sm + rr * 756;
        float iv = sigf(r[j]);
        float ov = sigf(r[j + 150]);
        float uv = tanhf(r[j + 300]);
        float f0 = sigf(r[450 + j]);
        float f1 = sigf(r[600 + j]);
        int orow = base + rr;
        float c0 = c_in[(2 * orow) * M + j];
        float c1 = c_in[(2 * orow + 1) * M + j];
        float cv = iv * uv + f0 * c0 + f1 * c1;
        float hv = ov * tanhf(cv);
        c_out[orow * M + j] = cv;
        h_out[orow * M + j] = hv;
    }
}

// ---------------------------------------------------------------------------
// Classifier: vec = [lh*rh, |lh-rh|]; mid = sig(vec@Wh + bh);
// out = log_softmax(mid@Wp + bp). One block (64 thr) per pair.
// ---------------------------------------------------------------------------
__global__ void __launch_bounds__(64) cls_kernel(
    const float* __restrict__ hfin,
    const float* __restrict__ Wh, const float* __restrict__ bh,
    const float* __restrict__ Wp, const float* __restrict__ bp,
    float* __restrict__ out)
{
    __shared__ float vec[2 * M];
    __shared__ float mid[HIDD];
    __shared__ float logits[NCC];

    const int q = blockIdx.x;
    const int t = threadIdx.x;
    const float* lh = hfin + q * M;
    const float* rh = hfin + (BH + q) * M;

    for (int j = t; j < M; j += 64) {
        float a = lh[j], b = rh[j];
        vec[j]     = a * b;
        vec[M + j] = fabsf(a - b);
    }
    __syncthreads();

    if (t < HIDD) {
        float s = bh[t];
        for (int j = 0; j < 2 * M; j++) s += vec[j] * Wh[j * HIDD + t];
        mid[t] = sigf(s);
    }
    __syncthreads();

    if (t < NCC) {
        float s = bp[t];
        for (int h = 0; h < HIDD; h++) s += mid[h] * Wp[h * NCC + t];
        logits[t] = s;
    }
    __syncthreads();

    if (t == 0) {
        float mx = logits[0];
        for (int c = 1; c < NCC; c++) mx = fmaxf(mx, logits[c]);
        float sum = 0.f;
        for (int c = 0; c < NCC; c++) sum += expf(logits[c] - mx);
        float lse = mx + logf(sum);
        for (int c = 0; c < NCC; c++) out[q * NCC + c] = logits[c] - lse;
    }
}

// ---------------------------------------------------------------------------
extern "C" void kernel_launch(void* const* d_in, const int* in_sizes, int n_in,
                              void* d_out, int out_size)
{
    (void)n_in; (void)out_size;
    const int*   ltok  = (const int*)d_in[0];
    const int*   rtok  = (const int*)d_in[1];
    const float* emb   = (const float*)d_in[2];
    const float* Wioux = (const float*)d_in[3];
    const float* bioux = (const float*)d_in[4];
    const float* Wiouh = (const float*)d_in[5];
    const float* biouh = (const float*)d_in[6];
    // d_in[7] = Wfx, d_in[8] = bfx : unused by the reference computation
    const float* Wfh   = (const float*)d_in[9];
    const float* bfh   = (const float*)d_in[10];
    const float* Wh    = (const float*)d_in[11];
    const float* bh    = (const float*)d_in[12];
    const float* Wp    = (const float*)d_in[13];
    const float* bp    = (const float*)d_in[14];
    float* out = (float*)d_out;

    const int V = in_sizes[2] / IND;

    void* p;
    float *hA, *cA, *hB, *cB, *table;
    cudaGetSymbolAddress(&p, g_table); table = (float*)p;
    cudaGetSymbolAddress(&p, g_hA); hA = (float*)p;
    cudaGetSymbolAddress(&p, g_cA); cA = (float*)p;
    cudaGetSymbolAddress(&p, g_hB); hB = (float*)p;
    cudaGetSymbolAddress(&p, g_cB); cB = (float*)p;

    // 1) Vocab-deduped leaf GEMM: table[v] = emb[v]@Wioux + bioux + biouh
    vocab_kernel<<<(V + VRT - 1) / VRT, 256>>>(emb, Wioux, bioux, biouh, table, V);

    // 2) Leaves: gate nonlinearities from table lookups
    leaf_lookup_kernel<<<(BQ * LVS * M) / 256, 256>>>(ltok, rtok, table, hA, cA);

    // 3) 6 tree levels, ping-pong A <-> B
    const float* hin = hA; const float* cin = cA;
    float* ho = hB; float* co = cB;
    for (int n_out = LVS / 2; n_out >= 1; n_out >>= 1) {
        tree_kernel<<<(BQ * n_out) / TRT, 256>>>(hin, cin, ho, co, Wiouh, biouh, Wfh, bfh);
        const float* th = hin; const float* tc = cin;
        hin = ho; cin = co;
        ho = (float*)th; co = (float*)tc;
    }
    // After 6 swaps, final state (4096 rows x 150) is back in g_hA

    // 4) Classifier
    cls_kernel<<<BH, 64>>>(hin, Wh, bh, Wp, bp, out);
}